// round 13
// baseline (speedup 1.0000x reference)
#include <cuda_runtime.h>
#include <cstdint>
#include <cstddef>

#define NN   2048
#define BB   32
#define COLS 8192   // B * F_IN * T

// scratch
__device__ float g_rhs[50331648];      // rhs[k][n][b*256+f*16+t]  (201 MB)
__device__ unsigned long long g_twT2[12288];  // packed (w,w) conv weights, c-minor
__device__ float g_chebR[12582912];    // tf32-rounded cheb  (50 MB)
__device__ float g_xR[16777216];       // tf32-rounded x     (67 MB)

// ---------------------------------------------------------------------------
__device__ __forceinline__ float to_tf32(float x) {
    uint32_t u;
    asm("cvt.rna.tf32.f32 %0, %1;" : "=r"(u) : "f"(x));
    return __uint_as_float(u);
}

__device__ __forceinline__ void mma4(float (&d)[4], const float (&a)[4], const float (&b)[2]) {
    const uint32_t* A = reinterpret_cast<const uint32_t*>(a);
    const uint32_t* B = reinterpret_cast<const uint32_t*>(b);
    asm volatile(
        "mma.sync.aligned.m16n8k8.row.col.f32.tf32.tf32.f32 "
        "{%0,%1,%2,%3},{%4,%5,%6,%7},{%8,%9},{%0,%1,%2,%3};\n"
        : "+f"(d[0]), "+f"(d[1]), "+f"(d[2]), "+f"(d[3])
        : "r"(A[0]), "r"(A[1]), "r"(A[2]), "r"(A[3]), "r"(B[0]), "r"(B[1]));
}

__device__ __forceinline__ void cpasync16(uint32_t dst, const void* src) {
    asm volatile("cp.async.cg.shared.global [%0], [%1], 16;\n" :: "r"(dst), "l"(src));
}

// packed f32x2 helpers (plain sm_100 feature, unlike tcgen05)
__device__ __forceinline__ uint64_t pk2(float lo, float hi) {
    uint64_t d; asm("mov.b64 %0, {%1, %2};" : "=l"(d) : "f"(lo), "f"(hi)); return d;
}
__device__ __forceinline__ void upk2(uint64_t v, float& lo, float& hi) {
    asm("mov.b64 {%0, %1}, %2;" : "=f"(lo), "=f"(hi) : "l"(v));
}
__device__ __forceinline__ uint64_t fma2(uint64_t a, uint64_t b, uint64_t c) {
    uint64_t d;
    asm("fma.rn.f32x2 %0, %1, %2, %3;" : "=l"(d) : "l"(a), "l"(b), "l"(c));
    return d;
}

// ---------------------------------------------------------------------------
// prep kernels
// ---------------------------------------------------------------------------
__global__ __launch_bounds__(256) void tr2_k(const float* __restrict__ tw) {
    const int i = blockIdx.x * 256 + threadIdx.x;   // i = c*192 + (ci*3+dt)
    const int c = i / 192;
    const int r = i % 192;
    const float w = tw[i];
    g_twT2[r * 64 + c] = pk2(w, w);
}

__global__ __launch_bounds__(256) void rnd_cheb_k(const float* __restrict__ s) {
    const int i = blockIdx.x * 256 + threadIdx.x;
    const float4 v = *((const float4*)s + i);
    *((float4*)g_chebR + i) = make_float4(to_tf32(v.x), to_tf32(v.y), to_tf32(v.z), to_tf32(v.w));
}
__global__ __launch_bounds__(256) void rnd_x_k(const float* __restrict__ s) {
    const int i = blockIdx.x * 256 + threadIdx.x;
    const float4 v = *((const float4*)s + i);
    *((float4*)g_xR + i) = make_float4(to_tf32(v.x), to_tf32(v.y), to_tf32(v.z), to_tf32(v.w));
}

// ---------------------------------------------------------------------------
// GEMM (R7, validated): rhs[k][n][col] = sum_m chebR[k][m][n] * xR[b][m][ft]
// ---------------------------------------------------------------------------
#define PADW 136
#define STG_F (16 * PADW)
#define SLOT_F (2 * STG_F)
#define GEMM_SMEM (3 * SLOT_F * 4)   // 52224 B

__global__ __launch_bounds__(128) void gemm_k3() {
    extern __shared__ float sm[];

    const int k    = blockIdx.z;
    const int n0   = blockIdx.y * 128;
    const int col0 = blockIdx.x * 128;
    const int b    = col0 >> 8;
    const int coff = col0 & 255;

    const int tid  = threadIdx.x;
    const int lane = tid & 31;
    const int warp = tid >> 5;
    const int wm   = (warp & 1) * 64;
    const int wn   = (warp >> 1) * 64;
    const int gid  = lane >> 2;
    const int tig  = lane & 3;

    const uint32_t smb = (uint32_t)__cvta_generic_to_shared(sm);
    const float* Abase = g_chebR + (size_t)k * NN * NN;
    const float* Bbase = g_xR + (size_t)b * NN * 256 + coff;

    float acc[4][8][4];
#pragma unroll
    for (int i = 0; i < 4; i++)
#pragma unroll
        for (int j = 0; j < 8; j++)
#pragma unroll
            for (int q = 0; q < 4; q++) acc[i][j][q] = 0.f;

    auto issue = [&](int sl, int kt) {
        const int m0 = kt * 16;
        const uint32_t base = smb + (uint32_t)(sl * SLOT_F) * 4;
#pragma unroll
        for (int j = 0; j < 4; j++) {
            const int id  = tid + j * 128;
            const int row = id >> 5;
            const int c16 = id & 31;
            cpasync16(base + (uint32_t)(row * PADW + c16 * 4) * 4,
                      Abase + (size_t)(m0 + row) * NN + n0 + c16 * 4);
            cpasync16(base + (uint32_t)(STG_F + row * PADW + c16 * 4) * 4,
                      Bbase + (size_t)(m0 + row) * 256 + c16 * 4);
        }
    };

    issue(0, 0);
    asm volatile("cp.async.commit_group;\n");
    issue(1, 1);
    asm volatile("cp.async.commit_group;\n");

    const int NIT = NN / 16;   // 128
    int sl = 0;
    for (int it = 0; it < NIT; ++it) {
        asm volatile("cp.async.wait_group 1;\n");
        __syncthreads();
        if (it + 2 < NIT) {
            issue(sl == 0 ? 2 : sl - 1, it + 2);
            asm volatile("cp.async.commit_group;\n");
        }

        const float* As = sm + sl * SLOT_F;
        const float* Bs = As + STG_F;
#pragma unroll
        for (int kk = 0; kk < 2; ++kk) {
            const int c0 = kk * 8 + tig;
            const int c1 = c0 + 4;
            float a[4][4];
            float bf[8][2];
#pragma unroll
            for (int fm = 0; fm < 4; ++fm) {
                const int r0 = wm + fm * 16 + gid;
                a[fm][0] = As[c0 * PADW + r0];
                a[fm][1] = As[c0 * PADW + r0 + 8];
                a[fm][2] = As[c1 * PADW + r0];
                a[fm][3] = As[c1 * PADW + r0 + 8];
            }
#pragma unroll
            for (int fn = 0; fn < 8; ++fn) {
                const int cc = wn + fn * 8 + gid;
                bf[fn][0] = Bs[c0 * PADW + cc];
                bf[fn][1] = Bs[c1 * PADW + cc];
            }
#pragma unroll
            for (int fm = 0; fm < 4; ++fm)
#pragma unroll
                for (int fn = 0; fn < 8; ++fn) mma4(acc[fm][fn], a[fm], bf[fn]);
        }
        sl = (sl == 2) ? 0 : sl + 1;
    }

    float* Cg = g_rhs + (size_t)k * NN * COLS;
#pragma unroll
    for (int fm = 0; fm < 4; ++fm) {
        const int r = n0 + wm + fm * 16 + gid;
#pragma unroll
        for (int fn = 0; fn < 8; ++fn) {
            const int cc = col0 + wn + fn * 8 + tig * 2;
            *(float2*)(Cg + (size_t)r * COLS + cc)       = make_float2(acc[fm][fn][0], acc[fm][fn][1]);
            *(float2*)(Cg + (size_t)(r + 8) * COLS + cc) = make_float2(acc[fm][fn][2], acc[fm][fn][3]);
        }
    }
}

// ---------------------------------------------------------------------------
// Epilogue v2: packed f32x2 math. Dynamic smem layout (floats):
//   Th[3072] | U[4096] | E[4*64*18] | O[4*64*20]   = 16896 floats = 67584 B
// E: even pairs (sv2j,sv2j+1); O: halo-shifted (O64[j] = (sv[2j-1], sv[2j])).
// ---------------------------------------------------------------------------
#define TH_OFF 0
#define U_OFF  3072
#define E_OFF  7168
#define O_OFF  11776
#define EPI_SMEM (16896 * 4)

__global__ __launch_bounds__(256) void epi_k2(const float* __restrict__ xg,
                                              const float* __restrict__ Theta,
                                              const float* __restrict__ tb,
                                              const float* __restrict__ rsw,
                                              const float* __restrict__ rsb,
                                              const float* __restrict__ lg,
                                              const float* __restrict__ lb,
                                              float* __restrict__ out) {
    extern __shared__ float sm[];
    float* Th = sm + TH_OFF;
    float* U  = sm + U_OFF;
    float* E  = sm + E_OFF;
    float* O  = sm + O_OFF;
    float* Sln = O;                 // LN stage aliases O after conv

    const int tid   = threadIdx.x;
    const int c     = tid & 63;
    const int nl    = tid >> 6;
    const int b     = blockIdx.x >> 7;
    const int nbase = (blockIdx.x & 127) * 16;
    const int lane  = tid & 31;

#pragma unroll
    for (int j = 0; j < 12; j++) Th[tid + j * 256] = Theta[tid + j * 256];

    float rw[16];
#pragma unroll
    for (int f = 0; f < 16; f++) rw[f] = rsw[c * 16 + f];
    const float bias0 = tb[c] + rsb[c];
    const uint64_t bias2 = pk2(bias0, bias0);

    const float g1 = lg[lane], g2 = lg[lane + 32];
    const float be1 = lb[lane], be2 = lb[lane + 32];

    for (int p = 0; p < 4; ++p) {
        // ---- cooperative load: rhs (768/n) and x (256/n)
#pragma unroll
        for (int j = 0; j < 3; j++) {
            const int idx = tid + j * 256;
            const int nll = idx / 192;
            const int li  = idx % 192;
            const int kk  = li >> 6;
            const int r4  = li & 63;
            const int nn  = nbase + p * 4 + nll;
            const float4 v = *(const float4*)(g_rhs + ((size_t)kk * NN + nn) * COLS +
                                              (size_t)b * 256 + r4 * 4);
            *(float4*)(U + idx * 4) = v;
        }
        {
            const int nll = tid >> 6, r4 = tid & 63;
            const int nn  = nbase + p * 4 + nll;
            const float4 v = *(const float4*)(xg + ((size_t)b * NN + nn) * 256 + r4 * 4);
            *(float4*)(U + 3072 + tid * 4) = v;
        }
        __syncthreads();

        // ---- spatial: s2[j] (packed t-pairs) = sum_kf Th[kf][c] * R[kf][pair j]
        uint64_t s2[8];
#pragma unroll
        for (int j = 0; j < 8; j++) s2[j] = 0ull;
        const float* Rr = U + nl * 768;
#pragma unroll 8
        for (int kf = 0; kf < 48; ++kf) {
            const uint64_t w2 = pk2(Th[kf * 64 + c], Th[kf * 64 + c]);
            const uint64_t* R2 = reinterpret_cast<const uint64_t*>(Rr + kf * 16);
#pragma unroll
            for (int j = 0; j < 8; j++) s2[j] = fma2(w2, R2[j], s2[j]);
        }

        // relu + stage into E (even pairs) and O (halo-shifted scalar layout)
        {
            uint64_t* Erow = reinterpret_cast<uint64_t*>(E + (nl * 64 + c) * 18);
            float* Orow = O + (nl * 64 + c) * 20;
            Orow[0] = 0.f; Orow[17] = 0.f;
#pragma unroll
            for (int j = 0; j < 8; j++) {
                float lo, hi; upk2(s2[j], lo, hi);
                lo = fmaxf(lo, 0.f); hi = fmaxf(hi, 0.f);
                Erow[j] = pk2(lo, hi);
                Orow[2 * j + 1] = lo;
                Orow[2 * j + 2] = hi;
            }
        }
        __syncthreads();

        // ---- h (packed): bias + residual 1x1 + time conv
        uint64_t h2[8];
#pragma unroll
        for (int j = 0; j < 8; j++) h2[j] = bias2;

        const float* Xr = U + 3072 + nl * 256;
#pragma unroll
        for (int f = 0; f < 16; f++) {
            const uint64_t w2 = pk2(rw[f], rw[f]);
            const uint64_t* X2 = reinterpret_cast<const uint64_t*>(Xr + f * 16);
#pragma unroll
            for (int j = 0; j < 8; j++) h2[j] = fma2(w2, X2[j], h2[j]);
        }

        {
            const uint64_t* Eb = reinterpret_cast<const uint64_t*>(E + nl * 1152);
            const float* Ob = O + nl * 1280;
#pragma unroll 2
            for (int ci = 0; ci < 64; ++ci) {
                const uint64_t w0p = __ldg((const unsigned long long*)g_twT2 + (ci * 3 + 0) * 64 + c);
                const uint64_t w1p = __ldg((const unsigned long long*)g_twT2 + (ci * 3 + 1) * 64 + c);
                const uint64_t w2p = __ldg((const unsigned long long*)g_twT2 + (ci * 3 + 2) * 64 + c);
                const uint64_t* Er = Eb + ci * 9;
                const uint64_t* Or = reinterpret_cast<const uint64_t*>(Ob + ci * 20);
                uint64_t o0 = Or[0];
#pragma unroll
                for (int j = 0; j < 8; j++) {
                    const uint64_t o1 = Or[j + 1];
                    h2[j] = fma2(w1p, Er[j], h2[j]);
                    h2[j] = fma2(w0p, o0, h2[j]);
                    h2[j] = fma2(w2p, o1, h2[j]);
                    o0 = o1;
                }
            }
        }
        __syncthreads();   // done reading U(X), E, O

        // ---- stage relu(h) into U as H[nl][t][c]
#pragma unroll
        for (int j = 0; j < 8; j++) {
            float lo, hi; upk2(h2[j], lo, hi);
            U[nl * 1024 + (2 * j) * 64 + c]     = fmaxf(lo, 0.f);
            U[nl * 1024 + (2 * j + 1) * 64 + c] = fmaxf(hi, 0.f);
        }
        __syncthreads();

        // ---- LayerNorm over c per (nl,t); write to Sln (=O region)
#pragma unroll
        for (int i = 0; i < 8; i++) {
            const int q   = (tid >> 5) * 8 + i;
            const int qnl = q >> 4, qt = q & 15;
            const float v1 = U[qnl * 1024 + qt * 64 + lane];
            const float v2 = U[qnl * 1024 + qt * 64 + lane + 32];
            float smv = v1 + v2, sq = v1 * v1 + v2 * v2;
#pragma unroll
            for (int o = 16; o > 0; o >>= 1) {
                smv += __shfl_xor_sync(0xffffffffu, smv, o);
                sq  += __shfl_xor_sync(0xffffffffu, sq, o);
            }
            const float mu  = smv * 0.015625f;
            const float var = sq * 0.015625f - mu * mu;
            const float rs  = rsqrtf(var + 1e-5f);
            Sln[qnl * 1088 + lane * 17 + qt]        = (v1 - mu) * rs * g1 + be1;
            Sln[qnl * 1088 + (lane + 32) * 17 + qt] = (v2 - mu) * rs * g2 + be2;
        }
        __syncthreads();

        // ---- coalesced copy-out
        {
            float* ob = out + (((size_t)b * NN + nbase + p * 4) << 10);
#pragma unroll
            for (int j = 0; j < 16; j++) {
                const int idx = tid + j * 256;
                const int qnl = idx >> 10;
                const int rem = idx & 1023;
                const int cc  = rem >> 4;
                const int tt  = rem & 15;
                ob[idx] = Sln[qnl * 1088 + cc * 17 + tt];
            }
        }
        __syncthreads();
    }
}

// ---------------------------------------------------------------------------
extern "C" void kernel_launch(void* const* d_in, const int* in_sizes, int n_in,
                              void* d_out, int out_size) {
    const float* x      = (const float*)d_in[0];
    const float* cheb   = (const float*)d_in[1];
    const float* Theta  = (const float*)d_in[2];
    const float* time_w = (const float*)d_in[3];
    const float* time_b = (const float*)d_in[4];
    const float* res_w  = (const float*)d_in[5];
    const float* res_b  = (const float*)d_in[6];
    const float* ln_g   = (const float*)d_in[7];
    const float* ln_b   = (const float*)d_in[8];
    float* out = (float*)d_out;

    cudaFuncSetAttribute(gemm_k3, cudaFuncAttributeMaxDynamicSharedMemorySize, GEMM_SMEM);
    cudaFuncSetAttribute(epi_k2, cudaFuncAttributeMaxDynamicSharedMemorySize, EPI_SMEM);

    tr2_k<<<48, 256>>>(time_w);
    rnd_cheb_k<<<12288, 256>>>(cheb);
    rnd_x_k<<<16384, 256>>>(x);

    dim3 g1(COLS / 128, NN / 128, 3);   // 64 x 16 x 3
    gemm_k3<<<g1, 128, GEMM_SMEM>>>();
    epi_k2<<<4096, 256, EPI_SMEM>>>(x, Theta, time_b, res_w, res_b, ln_g, ln_b, out);
}

// round 14
// speedup vs baseline: 1.4400x; 1.4400x over previous
#include <cuda_runtime.h>
#include <cstdint>
#include <cstddef>

#define NN   2048
#define BB   32
#define COLS 8192   // B * F_IN * T

// scratch
__device__ float g_rhs[50331648];   // rhs[k][n][b*256+f*16+t]  (201 MB)
__device__ float g_sp[67108864];    // spatial S[b][o][n*16+t]  (268 MB)
__device__ float g_wA[13312];       // merged A: rows 0..191 = tw dt-major, 192..207 = rsw^T
__device__ float g_chebR[12582912]; // tf32-rounded cheb  (50 MB)
__device__ float g_xR[16777216];    // tf32-rounded x     (67 MB)

// ---------------------------------------------------------------------------
__device__ __forceinline__ float to_tf32(float x) {
    uint32_t u;
    asm("cvt.rna.tf32.f32 %0, %1;" : "=r"(u) : "f"(x));
    return __uint_as_float(u);
}

__device__ __forceinline__ void mma4(float (&d)[4], const float (&a)[4], const float (&b)[2]) {
    const uint32_t* A = reinterpret_cast<const uint32_t*>(a);
    const uint32_t* B = reinterpret_cast<const uint32_t*>(b);
    asm volatile(
        "mma.sync.aligned.m16n8k8.row.col.f32.tf32.tf32.f32 "
        "{%0,%1,%2,%3},{%4,%5,%6,%7},{%8,%9},{%0,%1,%2,%3};\n"
        : "+f"(d[0]), "+f"(d[1]), "+f"(d[2]), "+f"(d[3])
        : "r"(A[0]), "r"(A[1]), "r"(A[2]), "r"(A[3]), "r"(B[0]), "r"(B[1]));
}

__device__ __forceinline__ void cpasync16(uint32_t dst, const void* src) {
    asm volatile("cp.async.cg.shared.global [%0], [%1], 16;\n" :: "r"(dst), "l"(src));
}

// ---------------------------------------------------------------------------
// prep kernels
// ---------------------------------------------------------------------------
// g_wA[r][c]: r<192: r = dt*64+ci -> tw[c*192 + ci*3 + dt]; r>=192: rsw[c*16 + (r-192)]
__global__ __launch_bounds__(256) void tr3_k(const float* __restrict__ tw,
                                             const float* __restrict__ rsw) {
    const int i = blockIdx.x * 256 + threadIdx.x;   // 13312 total
    if (i >= 13312) return;
    const int r = i >> 6;
    const int c = i & 63;
    float v;
    if (r < 192) {
        const int dt = r >> 6, ci = r & 63;
        v = tw[c * 192 + ci * 3 + dt];
    } else {
        v = rsw[c * 16 + (r - 192)];
    }
    g_wA[r * 64 + c] = v;
}

__global__ __launch_bounds__(256) void rnd_cheb_k(const float* __restrict__ s) {
    const int i = blockIdx.x * 256 + threadIdx.x;
    const float4 v = *((const float4*)s + i);
    *((float4*)g_chebR + i) = make_float4(to_tf32(v.x), to_tf32(v.y), to_tf32(v.z), to_tf32(v.w));
}
__global__ __launch_bounds__(256) void rnd_x_k(const float* __restrict__ s) {
    const int i = blockIdx.x * 256 + threadIdx.x;
    const float4 v = *((const float4*)s + i);
    *((float4*)g_xR + i) = make_float4(to_tf32(v.x), to_tf32(v.y), to_tf32(v.z), to_tf32(v.w));
}

// ---------------------------------------------------------------------------
// GEMM (R7, validated): rhs[k][n][col] = sum_m chebR[k][m][n] * xR[b][m][ft]
// ---------------------------------------------------------------------------
#define PADW 136
#define STG_F (16 * PADW)
#define SLOT_F (2 * STG_F)
#define GEMM_SMEM (3 * SLOT_F * 4)   // 52224 B

__global__ __launch_bounds__(128) void gemm_k3() {
    extern __shared__ float sm[];

    const int k    = blockIdx.z;
    const int n0   = blockIdx.y * 128;
    const int col0 = blockIdx.x * 128;
    const int b    = col0 >> 8;
    const int coff = col0 & 255;

    const int tid  = threadIdx.x;
    const int lane = tid & 31;
    const int warp = tid >> 5;
    const int wm   = (warp & 1) * 64;
    const int wn   = (warp >> 1) * 64;
    const int gid  = lane >> 2;
    const int tig  = lane & 3;

    const uint32_t smb = (uint32_t)__cvta_generic_to_shared(sm);
    const float* Abase = g_chebR + (size_t)k * NN * NN;
    const float* Bbase = g_xR + (size_t)b * NN * 256 + coff;

    float acc[4][8][4];
#pragma unroll
    for (int i = 0; i < 4; i++)
#pragma unroll
        for (int j = 0; j < 8; j++)
#pragma unroll
            for (int q = 0; q < 4; q++) acc[i][j][q] = 0.f;

    auto issue = [&](int sl, int kt) {
        const int m0 = kt * 16;
        const uint32_t base = smb + (uint32_t)(sl * SLOT_F) * 4;
#pragma unroll
        for (int j = 0; j < 4; j++) {
            const int id  = tid + j * 128;
            const int row = id >> 5;
            const int c16 = id & 31;
            cpasync16(base + (uint32_t)(row * PADW + c16 * 4) * 4,
                      Abase + (size_t)(m0 + row) * NN + n0 + c16 * 4);
            cpasync16(base + (uint32_t)(STG_F + row * PADW + c16 * 4) * 4,
                      Bbase + (size_t)(m0 + row) * 256 + c16 * 4);
        }
    };

    issue(0, 0);
    asm volatile("cp.async.commit_group;\n");
    issue(1, 1);
    asm volatile("cp.async.commit_group;\n");

    const int NIT = NN / 16;   // 128
    int sl = 0;
    for (int it = 0; it < NIT; ++it) {
        asm volatile("cp.async.wait_group 1;\n");
        __syncthreads();
        if (it + 2 < NIT) {
            issue(sl == 0 ? 2 : sl - 1, it + 2);
            asm volatile("cp.async.commit_group;\n");
        }

        const float* As = sm + sl * SLOT_F;
        const float* Bs = As + STG_F;
#pragma unroll
        for (int kk = 0; kk < 2; ++kk) {
            const int c0 = kk * 8 + tig;
            const int c1 = c0 + 4;
            float a[4][4];
            float bf[8][2];
#pragma unroll
            for (int fm = 0; fm < 4; ++fm) {
                const int r0 = wm + fm * 16 + gid;
                a[fm][0] = As[c0 * PADW + r0];
                a[fm][1] = As[c0 * PADW + r0 + 8];
                a[fm][2] = As[c1 * PADW + r0];
                a[fm][3] = As[c1 * PADW + r0 + 8];
            }
#pragma unroll
            for (int fn = 0; fn < 8; ++fn) {
                const int cc = wn + fn * 8 + gid;
                bf[fn][0] = Bs[c0 * PADW + cc];
                bf[fn][1] = Bs[c1 * PADW + cc];
            }
#pragma unroll
            for (int fm = 0; fm < 4; ++fm)
#pragma unroll
                for (int fn = 0; fn < 8; ++fn) mma4(acc[fm][fn], a[fm], bf[fn]);
        }
        sl = (sl == 2) ? 0 : sl + 1;
    }

    float* Cg = g_rhs + (size_t)k * NN * COLS;
#pragma unroll
    for (int fm = 0; fm < 4; ++fm) {
        const int r = n0 + wm + fm * 16 + gid;
#pragma unroll
        for (int fn = 0; fn < 8; ++fn) {
            const int cc = col0 + wn + fn * 8 + tig * 2;
            *(float2*)(Cg + (size_t)r * COLS + cc)       = make_float2(acc[fm][fn][0], acc[fm][fn][1]);
            *(float2*)(Cg + (size_t)(r + 8) * COLS + cc) = make_float2(acc[fm][fn][2], acc[fm][fn][3]);
        }
    }
}

// ---------------------------------------------------------------------------
// s2_k: S[b][o][(n,t)] = relu( sum_kf Theta[kf][o] * rhs[k][n][b,f,t] )
// M=64(o), K=48, CTA N=128 cols (8 n x 16 t), 4 warps x 32 cols.
// ---------------------------------------------------------------------------
#define S2_APAD 72
#define S2_BPAD 136

__global__ __launch_bounds__(128) void s2_k(const float* __restrict__ Theta) {
    __shared__ float Th2[48 * S2_APAD];   // A: [kf][o] rows      (13.8 KB)
    __shared__ float Bs[48 * S2_BPAD];    // B: [kf][(nl,t)] rows (26.1 KB)

    const int nb = blockIdx.x & 255;
    const int b  = blockIdx.x >> 8;
    const int n0 = nb * 8;

    const int tid  = threadIdx.x;
    const int lane = tid & 31;
    const int wid  = tid >> 5;
    const int wn   = wid * 32;
    const int gid  = lane >> 2;
    const int tig  = lane & 3;

    const uint32_t thb = (uint32_t)__cvta_generic_to_shared(Th2);
    const uint32_t bsb = (uint32_t)__cvta_generic_to_shared(Bs);

    // stage A: Theta 48x64, contiguous source
#pragma unroll
    for (int j = 0; j < 6; j++) {
        const int q = tid + j * 128;        // float4 id 0..767
        const int r = q >> 4, c4 = q & 15;
        cpasync16(thb + (uint32_t)(r * S2_APAD + c4 * 4) * 4, Theta + q * 4);
    }
    // stage B: rows (k,f), 8 n-segments of 16 floats
#pragma unroll
    for (int j = 0; j < 12; j++) {
        const int q  = tid + j * 128;       // 0..1535
        const int s  = q >> 2, c16 = q & 3;
        const int r  = s >> 3, nl = s & 7;
        const int k  = r >> 4, f = r & 15;
        const float* src = g_rhs + (size_t)k * NN * COLS + (size_t)(n0 + nl) * COLS +
                           (size_t)b * 256 + f * 16 + c16 * 4;
        cpasync16(bsb + (uint32_t)(r * S2_BPAD + nl * 16 + c16 * 4) * 4, src);
    }
    asm volatile("cp.async.commit_group;\n");
    asm volatile("cp.async.wait_group 0;\n");
    __syncthreads();

    float acc[4][4][4];
#pragma unroll
    for (int i = 0; i < 4; i++)
#pragma unroll
        for (int j = 0; j < 4; j++)
#pragma unroll
            for (int q = 0; q < 4; q++) acc[i][j][q] = 0.f;

#pragma unroll
    for (int ko = 0; ko < 6; ++ko) {
        const int c0 = ko * 8 + tig;
        const int c1 = c0 + 4;
        float a[4][4];
        float bf[4][2];
#pragma unroll
        for (int fm = 0; fm < 4; ++fm) {
            const int r0 = fm * 16 + gid;
            a[fm][0] = Th2[c0 * S2_APAD + r0];
            a[fm][1] = Th2[c0 * S2_APAD + r0 + 8];
            a[fm][2] = Th2[c1 * S2_APAD + r0];
            a[fm][3] = Th2[c1 * S2_APAD + r0 + 8];
        }
#pragma unroll
        for (int fn = 0; fn < 4; ++fn) {
            const int cc = wn + fn * 8 + gid;
            bf[fn][0] = Bs[c0 * S2_BPAD + cc];
            bf[fn][1] = Bs[c1 * S2_BPAD + cc];
        }
#pragma unroll
        for (int fm = 0; fm < 4; ++fm)
#pragma unroll
            for (int fn = 0; fn < 4; ++fn) mma4(acc[fm][fn], a[fm], bf[fn]);
    }

    // store with relu: g_sp[b][o][n0*16 + col]
#pragma unroll
    for (int fm = 0; fm < 4; ++fm) {
        const int o1 = fm * 16 + gid;
#pragma unroll
        for (int fn = 0; fn < 4; ++fn) {
            const int cc = wn + fn * 8 + tig * 2;
            float* d1 = g_sp + ((size_t)b * 64 + o1) * 32768 + n0 * 16 + cc;
            float* d2 = g_sp + ((size_t)b * 64 + o1 + 8) * 32768 + n0 * 16 + cc;
            *(float2*)d1 = make_float2(fmaxf(acc[fm][fn][0], 0.f), fmaxf(acc[fm][fn][1], 0.f));
            *(float2*)d2 = make_float2(fmaxf(acc[fm][fn][2], 0.f), fmaxf(acc[fm][fn][3], 0.f));
        }
    }
}

// ---------------------------------------------------------------------------
// c2_k: h[c][(n,t)] = sum_{r<192} wA[r][c]*Spad + sum_f wA[192+f][c]*X
//       then +bias, relu, LayerNorm over c, transpose-store.
// CTA: 128 cols (8 n x 16 t), one b. 4 warps x 32 cols, M=64.
// smem (floats): Ws[208*72] | Spad[64*152] | Xs[16*136]
// ---------------------------------------------------------------------------
#define C2_WS   0
#define C2_SP   (208 * 72)                 // 14976
#define C2_XS   (C2_SP + 64 * 152)         // 24704
#define C2_TOT  (C2_XS + 16 * 136)         // 26880 floats
#define C2_SMEM (C2_TOT * 4)               // 107520 B
#define SPW 152

__global__ __launch_bounds__(128) void c2_k(const float* __restrict__ xg,
                                            const float* __restrict__ tb,
                                            const float* __restrict__ rsb,
                                            const float* __restrict__ lg,
                                            const float* __restrict__ lb,
                                            float* __restrict__ out) {
    extern __shared__ float sm[];
    float* Ws   = sm + C2_WS;
    float* Spad = sm + C2_SP;
    float* Xs   = sm + C2_XS;
    float* Hs   = Spad;        // [col][c] stride 65, reused after mma
    float* Sln  = Ws;          // [nl*1088 + c*17 + t], reused after mma

    const int nb = blockIdx.x & 255;
    const int b  = blockIdx.x >> 8;
    const int n0 = nb * 8;

    const int tid  = threadIdx.x;
    const int lane = tid & 31;
    const int wid  = tid >> 5;
    const int wn   = wid * 32;
    const int gid  = lane >> 2;
    const int tig  = lane & 3;

    const uint32_t wsb = (uint32_t)__cvta_generic_to_shared(Ws);
    const uint32_t xsb = (uint32_t)__cvta_generic_to_shared(Xs);

    // ---- stage Ws (208x64) via cp.async
#pragma unroll
    for (int j = 0; j < 26; j++) {
        const int q = tid + j * 128;        // float4 id 0..3327
        const int r = q >> 4, c4 = q & 15;
        cpasync16(wsb + (uint32_t)(r * 72 + c4 * 4) * 4, g_wA + r * 64 + c4 * 4);
    }
    // ---- stage Xs (16 f x 8 n x 16 t)
    {
        const int f = tid >> 3, nl = tid & 7;
        const float* src = xg + ((size_t)b * NN + n0 + nl) * 256 + f * 16;
#pragma unroll
        for (int c4 = 0; c4 < 4; c4++)
            cpasync16(xsb + (uint32_t)(f * 136 + nl * 16 + c4 * 4) * 4, src + c4 * 4);
    }
    asm volatile("cp.async.commit_group;\n");

    // ---- stage Spad (64 ci x 8 n), halo-padded rows [ci][nl*18 + 1..16], zeros at 0,17
#pragma unroll
    for (int j = 0; j < 4; j++) {
        const int s  = tid + j * 128;       // 0..511
        const int ci = s >> 3, nl = s & 7;
        float* drow = Spad + ci * SPW + nl * 18;
        drow[0] = 0.f; drow[17] = 0.f;
        const float* src = g_sp + ((size_t)b * 64 + ci) * 32768 + (size_t)(n0 + nl) * 16;
#pragma unroll
        for (int c4 = 0; c4 < 4; c4++) {
            const float4 v = *(const float4*)(src + c4 * 4);
            drow[1 + c4 * 4 + 0] = to_tf32(v.x);
            drow[1 + c4 * 4 + 1] = to_tf32(v.y);
            drow[1 + c4 * 4 + 2] = to_tf32(v.z);
            drow[1 + c4 * 4 + 3] = to_tf32(v.w);
        }
    }
    asm volatile("cp.async.wait_group 0;\n");
    __syncthreads();

    // ---- bias preload for this thread's 8 c-rows
    float biasA[4], biasB[4];
#pragma unroll
    for (int fm = 0; fm < 4; fm++) {
        const int ca = fm * 16 + gid;
        biasA[fm] = tb[ca] + rsb[ca];
        biasB[fm] = tb[ca + 8] + rsb[ca + 8];
    }
    const float g1 = lg[lane], g2 = lg[lane + 32];
    const float be1 = lb[lane], be2 = lb[lane + 32];

    // per-fn column offsets
    int colA[4], ccL[4];
#pragma unroll
    for (int fn = 0; fn < 4; fn++) {
        const int cc = wn + fn * 8 + gid;
        ccL[fn]  = cc;
        colA[fn] = (cc >> 4) * 18 + (cc & 15);
    }

    float acc[4][4][4];
#pragma unroll
    for (int i = 0; i < 4; i++)
#pragma unroll
        for (int j = 0; j < 4; j++)
#pragma unroll
            for (int q = 0; q < 4; q++) acc[i][j][q] = 0.f;

    // ---- conv part: K rows 0..191 (dt-major)
#pragma unroll 4
    for (int ko = 0; ko < 24; ++ko) {
        const int c0  = ko * 8 + tig;
        const int c1  = c0 + 4;
        const int dt  = ko >> 3;
        const int ci0 = (ko & 7) * 8 + tig;
        const int ci1 = ci0 + 4;
        float a[4][4];
        float bf[4][2];
#pragma unroll
        for (int fm = 0; fm < 4; ++fm) {
            const int r0 = fm * 16 + gid;
            a[fm][0] = Ws[c0 * 72 + r0];
            a[fm][1] = Ws[c0 * 72 + r0 + 8];
            a[fm][2] = Ws[c1 * 72 + r0];
            a[fm][3] = Ws[c1 * 72 + r0 + 8];
        }
#pragma unroll
        for (int fn = 0; fn < 4; ++fn) {
            bf[fn][0] = Spad[ci0 * SPW + colA[fn] + dt];
            bf[fn][1] = Spad[ci1 * SPW + colA[fn] + dt];
        }
#pragma unroll
        for (int fm = 0; fm < 4; ++fm)
#pragma unroll
            for (int fn = 0; fn < 4; ++fn) mma4(acc[fm][fn], a[fm], bf[fn]);
    }
    // ---- residual part: K rows 192..207 (X)
#pragma unroll
    for (int ko = 24; ko < 26; ++ko) {
        const int c0 = ko * 8 + tig;
        const int c1 = c0 + 4;
        const int f0 = (ko - 24) * 8 + tig;
        const int f1 = f0 + 4;
        float a[4][4];
        float bf[4][2];
#pragma unroll
        for (int fm = 0; fm < 4; ++fm) {
            const int r0 = fm * 16 + gid;
            a[fm][0] = Ws[c0 * 72 + r0];
            a[fm][1] = Ws[c0 * 72 + r0 + 8];
            a[fm][2] = Ws[c1 * 72 + r0];
            a[fm][3] = Ws[c1 * 72 + r0 + 8];
        }
#pragma unroll
        for (int fn = 0; fn < 4; ++fn) {
            bf[fn][0] = Xs[f0 * 136 + ccL[fn]];
            bf[fn][1] = Xs[f1 * 136 + ccL[fn]];
        }
#pragma unroll
        for (int fm = 0; fm < 4; ++fm)
#pragma unroll
            for (int fn = 0; fn < 4; ++fn) mma4(acc[fm][fn], a[fm], bf[fn]);
    }
    __syncthreads();   // all Spad/Xs/Ws reads done

    // ---- bias + relu, stage into Hs[col][c] (stride 65)
#pragma unroll
    for (int fm = 0; fm < 4; ++fm) {
        const int ca = fm * 16 + gid;
        const int cb = ca + 8;
#pragma unroll
        for (int fn = 0; fn < 4; ++fn) {
            const int col0 = wn + fn * 8 + tig * 2;
            Hs[col0 * 65 + ca]       = fmaxf(acc[fm][fn][0] + biasA[fm], 0.f);
            Hs[(col0 + 1) * 65 + ca] = fmaxf(acc[fm][fn][1] + biasA[fm], 0.f);
            Hs[col0 * 65 + cb]       = fmaxf(acc[fm][fn][2] + biasB[fm], 0.f);
            Hs[(col0 + 1) * 65 + cb] = fmaxf(acc[fm][fn][3] + biasB[fm], 0.f);
        }
    }
    __syncthreads();

    // ---- LayerNorm over c per col; write to Sln[nl*1088 + c*17 + t]
#pragma unroll 1
    for (int i = 0; i < 32; i++) {
        const int col = wid * 32 + i;
        const int nl = col >> 4, t = col & 15;
        const float v1 = Hs[col * 65 + lane];
        const float v2 = Hs[col * 65 + lane + 32];
        float smv = v1 + v2, sq = v1 * v1 + v2 * v2;
#pragma unroll
        for (int o = 16; o > 0; o >>= 1) {
            smv += __shfl_xor_sync(0xffffffffu, smv, o);
            sq  += __shfl_xor_sync(0xffffffffu, sq, o);
        }
        const float mu  = smv * 0.015625f;
        const float var = sq * 0.015625f - mu * mu;
        const float rs  = rsqrtf(var + 1e-5f);
        Sln[nl * 1088 + lane * 17 + t]        = (v1 - mu) * rs * g1 + be1;
        Sln[nl * 1088 + (lane + 32) * 17 + t] = (v2 - mu) * rs * g2 + be2;
    }
    __syncthreads();

    // ---- coalesced copy-out: out[b][n0+nl][c][t], 8192 contiguous floats
    {
        float* ob = out + ((size_t)b * NN + n0) * 1024;
#pragma unroll
        for (int j = 0; j < 16; j++) {
            const int q = tid + j * 128;       // float4 id 0..2047
            const int idx = q * 4;
            const int nl = idx >> 10;
            const int rem = idx & 1023;
            const int cc = rem >> 4, tt = rem & 15;
            const float* s0 = Sln + nl * 1088 + cc * 17 + tt;
            *(float4*)(ob + idx) = make_float4(s0[0], s0[1], s0[2], s0[3]);
        }
    }
}

// ---------------------------------------------------------------------------
extern "C" void kernel_launch(void* const* d_in, const int* in_sizes, int n_in,
                              void* d_out, int out_size) {
    const float* x      = (const float*)d_in[0];
    const float* cheb   = (const float*)d_in[1];
    const float* Theta  = (const float*)d_in[2];
    const float* time_w = (const float*)d_in[3];
    const float* time_b = (const float*)d_in[4];
    const float* res_w  = (const float*)d_in[5];
    const float* res_b  = (const float*)d_in[6];
    const float* ln_g   = (const float*)d_in[7];
    const float* ln_b   = (const float*)d_in[8];
    float* out = (float*)d_out;

    cudaFuncSetAttribute(gemm_k3, cudaFuncAttributeMaxDynamicSharedMemorySize, GEMM_SMEM);
    cudaFuncSetAttribute(c2_k, cudaFuncAttributeMaxDynamicSharedMemorySize, C2_SMEM);

    tr3_k<<<52, 256>>>(time_w, res_w);
    rnd_cheb_k<<<12288, 256>>>(cheb);
    rnd_x_k<<<16384, 256>>>(x);

    dim3 g1(COLS / 128, NN / 128, 3);   // 64 x 16 x 3
    gemm_k3<<<g1, 128, GEMM_SMEM>>>();
    s2_k<<<8192, 128>>>(Theta);
    c2_k<<<8192, 128, C2_SMEM>>>(x, time_b, res_b, ln_g, ln_b, out);
}